// round 12
// baseline (speedup 1.0000x reference)
#include <cuda_runtime.h>
#include <cuda_fp16.h>
#include <math.h>
#include <cstdint>

#define NN 50000
#define NE 600000
#define NG 64

typedef unsigned long long u64;
typedef unsigned int u32;

// ---------------- scratch (device globals; allocation-free) ----------------
__device__ __half d_xh   [(size_t)NN * 128];
__device__ __half d_h1lin[(size_t)NN * 512];
__device__ __half d_xcat [(size_t)NN * 512];
__device__ __half d_h2lin[(size_t)NN * 256];
__device__ __half d_h2   [(size_t)NN * 256];
__device__ __half d_h3lin[(size_t)NN * 128];
__device__ float  d_h3   [(size_t)NN * 128];
__device__ unsigned short d_wc_hi[512 * 128], d_wc_lo[512 * 128];
__device__ unsigned short d_w2_hi[256 * 512], d_w2_lo[256 * 512];
__device__ unsigned short d_w3_hi[128 * 256], d_w3_lo[128 * 256];
__device__ float d_dis4[4 * NN];
__device__ float d_dis1[NN];
__device__ int   d_cnt[NN];
__device__ int   d_rowptr[NN + 1];
__device__ int   d_wrptr[NN];
__device__ int   d_csr_src[NE];
__device__ float4 d_csr_nrm4[NE];
__device__ float  d_csr_nrm1[NE];
__device__ int   d_bsum[256];
__device__ int   d_boff[256];
__device__ int   d_gstart[NG + 1];
__device__ float d_gmat[NG * 256];

__device__ __forceinline__ u32 smem_u32(const void* p) {
    u32 a;
    asm("{ .reg .u64 t; cvta.to.shared.u64 t, %1; cvt.u32.u64 %0, t; }" : "=r"(a) : "l"(p));
    return a;
}

__device__ __forceinline__ void splitf16(float a, unsigned short& h, unsigned short& l) {
    __half hh = __float2half_rn(a);
    float r = a - __half2float(hh);
    __half ll = __float2half_rn(r);
    h = *reinterpret_cast<unsigned short*>(&hh);
    l = *reinterpret_cast<unsigned short*>(&ll);
}

__device__ __forceinline__ void mma_f16(float* d, const u32* a, const u32* b) {
    asm volatile(
        "mma.sync.aligned.m16n8k16.row.col.f32.f16.f16.f32 "
        "{%0,%1,%2,%3}, {%4,%5,%6,%7}, {%8,%9}, {%0,%1,%2,%3};"
        : "+f"(d[0]), "+f"(d[1]), "+f"(d[2]), "+f"(d[3])
        : "r"(a[0]), "r"(a[1]), "r"(a[2]), "r"(a[3]), "r"(b[0]), "r"(b[1]));
}

__device__ __forceinline__ void ldm4(u32* d, u32 addr) {
    asm volatile("ldmatrix.sync.aligned.m8n8.x4.shared.b16 {%0,%1,%2,%3}, [%4];"
        : "=r"(d[0]), "=r"(d[1]), "=r"(d[2]), "=r"(d[3]) : "r"(addr));
}

__device__ __forceinline__ void cpa16(u32 dst, const void* src, bool full) {
    int sz = full ? 16 : 0;
    asm volatile("cp.async.ca.shared.global [%0], [%1], 16, %2;"
        :: "r"(dst), "l"(src), "r"(sz));
}
#define CPA_COMMIT() asm volatile("cp.async.commit_group;" ::: "memory")
#define CPA_WAIT(n)  asm volatile("cp.async.wait_group %0;" :: "n"(n) : "memory")

__device__ __forceinline__ void fma_h4(float4& acc, const __half* p, float n) {
    uint2 raw = *(const uint2*)p;
    __half2 p0 = *reinterpret_cast<__half2*>(&raw.x);
    __half2 p1 = *reinterpret_cast<__half2*>(&raw.y);
    float2 f0 = __half22float2(p0);
    float2 f1 = __half22float2(p1);
    acc.x += f0.x * n; acc.y += f0.y * n;
    acc.z += f1.x * n; acc.w += f1.y * n;
}

__device__ __forceinline__ void st_h4(__half* p, float4 o) {
    union { __half2 h2[2]; uint2 u; } cv;
    cv.h2[0] = __floats2half2_rn(o.x, o.y);
    cv.h2[1] = __floats2half2_rn(o.z, o.w);
    *(uint2*)p = cv.u;
}

// ---------------- setup ----------------
__global__ void k_init(const float* __restrict__ WA, const float* __restrict__ WB,
                       const float* __restrict__ WC, const float* __restrict__ WD,
                       const float* __restrict__ W2, const float* __restrict__ W3) {
    int b = blockIdx.x;
    if (b < 196) {
        int v = b * 256 + threadIdx.x;
        if (v < NN) {
            d_dis4[v] = 1.0f; d_dis4[NN + v] = 1.0f;
            d_dis4[2 * NN + v] = 1.0f; d_dis4[3 * NN + v] = 1.0f;
            d_dis1[v] = 1.0f;
        }
        return;
    }
    int i = (b - 196) * 256 + threadIdx.x;
    float v; unsigned short h, l;
    if (i < 65536) {
        int n = i >> 7, kk = i & 127;
        int conv = n >> 7, c = n & 127;
        const float* W = (conv == 0) ? WA : (conv == 1) ? WB : (conv == 2) ? WC : WD;
        v = W[kk * 128 + c];
        splitf16(v, h, l);
        d_wc_hi[i] = h; d_wc_lo[i] = l;
    } else if (i < 65536 + 131072) {
        int j = i - 65536;
        int n = j >> 9, kk = j & 511;
        v = W2[kk * 256 + n];
        splitf16(v, h, l);
        d_w2_hi[j] = h; d_w2_lo[j] = l;
    } else {
        int j = i - 196608;
        int n = j >> 8, kk = j & 255;
        v = W3[kk * 128 + n];
        splitf16(v, h, l);
        d_w3_hi[j] = h; d_w3_lo[j] = l;
    }
}

__global__ void k_x2h(const float* __restrict__ x) {
    int i = blockIdx.x * blockDim.x + threadIdx.x;
    if (i >= NN * 16) return;
    float4 f0 = *(const float4*)(x + (size_t)i * 8);
    float4 f1 = *(const float4*)(x + (size_t)i * 8 + 4);
    union { __half2 h2[4]; uint4 u; } cv;
    cv.h2[0] = __floats2half2_rn(f0.x, f0.y);
    cv.h2[1] = __floats2half2_rn(f0.z, f0.w);
    cv.h2[2] = __floats2half2_rn(f1.x, f1.y);
    cv.h2[3] = __floats2half2_rn(f1.z, f1.w);
    *(uint4*)(d_xh + (size_t)i * 8) = cv.u;
}

__global__ void k_degree(const int* __restrict__ ei, const float* __restrict__ ea) {
    int e = blockIdx.x * blockDim.x + threadIdx.x;
    if (e >= NE) return;
    int dst = ei[NE + e];
    float4 w = __ldg((const float4*)ea + e);
    atomicAdd(&d_dis4[dst], w.x);
    atomicAdd(&d_dis4[NN + dst], w.y);
    atomicAdd(&d_dis4[2 * NN + dst], w.z);
    atomicAdd(&d_dis4[3 * NN + dst], w.w);
    atomicAdd(&d_dis1[dst], 1.0f);
}

__global__ void k_rsqrt() {
    int v = blockIdx.x * blockDim.x + threadIdx.x;
    if (v < 4 * NN) {
        d_dis4[v] = rsqrtf(d_dis4[v]);
    } else if (v < 5 * NN) {
        int u = v - 4 * NN;
        float deg = d_dis1[u];
        d_cnt[u] = (int)(deg - 0.5f);
        d_dis1[u] = rsqrtf(deg);
    }
}

// ---------------- 3-phase grid scan ----------------
__global__ void k_bsum() {
    __shared__ int ws[8];
    int idx = blockIdx.x * 256 + threadIdx.x;
    int v = (idx < NN) ? d_cnt[idx] : 0;
    int lane = threadIdx.x & 31, wid = threadIdx.x >> 5;
    int s = v;
    #pragma unroll
    for (int o = 16; o > 0; o >>= 1) s += __shfl_down_sync(0xffffffffu, s, o);
    if (lane == 0) ws[wid] = s;
    __syncthreads();
    if (wid == 0) {
        int t = (lane < 8) ? ws[lane] : 0;
        #pragma unroll
        for (int o = 4; o > 0; o >>= 1) t += __shfl_down_sync(0xffffffffu, t, o);
        if (lane == 0) d_bsum[blockIdx.x] = t;
    }
}

__global__ void k_bscan() {
    __shared__ int ws[8];
    int t = threadIdx.x;
    int lane = t & 31, wid = t >> 5;
    int v = (t < 196) ? d_bsum[t] : 0;
    int x = v;
    #pragma unroll
    for (int o = 1; o < 32; o <<= 1) {
        int y = __shfl_up_sync(0xffffffffu, x, o);
        if (lane >= o) x += y;
    }
    if (lane == 31) ws[wid] = x;
    __syncthreads();
    if (wid == 0 && lane < 8) {
        int s = ws[lane];
        #pragma unroll
        for (int o = 1; o < 8; o <<= 1) {
            int y = __shfl_up_sync(0xffu, s, o);
            if (lane >= o) s += y;
        }
        ws[lane] = s;
    }
    __syncthreads();
    int excl = x - v + (wid > 0 ? ws[wid - 1] : 0);
    if (t < 196) d_boff[t] = excl;
    if (t == 0) d_rowptr[NN] = NE;
}

__global__ void k_scan3() {
    __shared__ int ws[8];
    int idx = blockIdx.x * 256 + threadIdx.x;
    int t = threadIdx.x;
    int lane = t & 31, wid = t >> 5;
    int v = (idx < NN) ? d_cnt[idx] : 0;
    int x = v;
    #pragma unroll
    for (int o = 1; o < 32; o <<= 1) {
        int y = __shfl_up_sync(0xffffffffu, x, o);
        if (lane >= o) x += y;
    }
    if (lane == 31) ws[wid] = x;
    __syncthreads();
    if (wid == 0 && lane < 8) {
        int s = ws[lane];
        #pragma unroll
        for (int o = 1; o < 8; o <<= 1) {
            int y = __shfl_up_sync(0xffu, s, o);
            if (lane >= o) s += y;
        }
        ws[lane] = s;
    }
    __syncthreads();
    int excl = x - v + (wid > 0 ? ws[wid - 1] : 0) + d_boff[blockIdx.x];
    if (idx < NN) { d_rowptr[idx] = excl; d_wrptr[idx] = excl; }
}

__global__ void k_scatter(const int* __restrict__ ei, const float* __restrict__ ea) {
    int e = blockIdx.x * blockDim.x + threadIdx.x;
    if (e >= NE) return;
    int src = ei[e];
    int dst = ei[NE + e];
    float4 w = __ldg((const float4*)ea + e);
    int pos = atomicAdd(&d_wrptr[dst], 1);
    float4 n4;
    n4.x = d_dis4[src] * w.x * d_dis4[dst];
    n4.y = d_dis4[NN + src] * w.y * d_dis4[NN + dst];
    n4.z = d_dis4[2 * NN + src] * w.z * d_dis4[2 * NN + dst];
    n4.w = d_dis4[3 * NN + src] * w.w * d_dis4[3 * NN + dst];
    d_csr_src[pos] = src;
    d_csr_nrm4[pos] = n4;
    d_csr_nrm1[pos] = d_dis1[src] * d_dis1[dst];
}

// ==== fp16 2-term GEMM, cp.async double-buffered: C = A @ (Bhi+Blo)^T ====
#define KT 16
#define ASTR 24
#define TILE_H (128 * ASTR)   // halves per buffer

__global__ __launch_bounds__(512, 1) void mma_gemm(
    const __half* __restrict__ A, const unsigned short* __restrict__ Bhi,
    const unsigned short* __restrict__ Blo, __half* __restrict__ C,
    int M, int K, int ldc)
{
    __shared__ unsigned short sA [2][TILE_H];
    __shared__ unsigned short sBh[2][TILE_H];
    __shared__ unsigned short sBl[2][TILE_H];
    int tid = threadIdx.x;
    int wid = tid >> 5, lane = tid & 31;
    int g = lane >> 2, tg = lane & 3;
    int wm = wid >> 2, wn = wid & 3;
    int row0 = blockIdx.y * 128, col0 = blockIdx.x * 128;

    u32 bA = smem_u32(sA), bBh = smem_u32(sBh), bBl = smem_u32(sBl);
    u32 aOff = (u32)(((wm * 32 + (lane & 15)) * ASTR + ((lane >> 4) << 3)) * 2);
    u32 bOff = (u32)(((wn * 32 + lane) * ASTR) * 2);

    // loader indices: op i (0..255): row=i>>1, seg=i&1 (16B = 8 halves)
    int li = tid & 255;
    int lrow = li >> 1, lseg = li & 1;
    u32 sm_off = (u32)((lrow * ASTR + lseg * 8) * 2);
    bool gA_ok = (row0 + lrow) < M;
    const __half* gAp = A + (gA_ok ? ((size_t)(row0 + lrow) * K + lseg * 8) : 0);
    size_t gBi = (size_t)(col0 + lrow) * K + lseg * 8;

    float c[2][4][4];
    #pragma unroll
    for (int mi = 0; mi < 2; mi++)
        #pragma unroll
        for (int ni = 0; ni < 4; ni++)
            #pragma unroll
            for (int q = 0; q < 4; q++) c[mi][ni][q] = 0.f;

    int nk = K / KT;
    // preload tile 0 into buf 0
    if (tid < 256) {
        cpa16(bA + sm_off, gAp, gA_ok);
        cpa16(bBh + sm_off, Bhi + gBi, true);
    } else {
        cpa16(bBl + sm_off, Blo + gBi, true);
    }
    CPA_COMMIT();

    for (int kt = 0; kt < nk; ++kt) {
        int buf = kt & 1;
        if (kt + 1 < nk) {
            u32 bofs = (u32)((buf ^ 1) * TILE_H * 2);
            int ko = (kt + 1) * KT;
            if (tid < 256) {
                cpa16(bA + bofs + sm_off, gAp + ko, gA_ok);
                cpa16(bBh + bofs + sm_off, Bhi + gBi + ko, true);
            } else {
                cpa16(bBl + bofs + sm_off, Blo + gBi + ko, true);
            }
            CPA_COMMIT();
            CPA_WAIT(1);
        } else {
            CPA_WAIT(0);
        }
        __syncthreads();
        u32 cofs = (u32)(buf * TILE_H * 2);
        u32 ah[2][4], bh0[4], bh1[4], bl0[4], bl1[4];
        ldm4(ah[0], bA + cofs + aOff);
        ldm4(ah[1], bA + cofs + aOff + 16 * ASTR * 2);
        ldm4(bh0, bBh + cofs + bOff);
        ldm4(bh1, bBh + cofs + bOff + 16);
        ldm4(bl0, bBl + cofs + bOff);
        ldm4(bl1, bBl + cofs + bOff + 16);
        #pragma unroll
        for (int mi = 0; mi < 2; mi++)
            #pragma unroll
            for (int ni = 0; ni < 4; ni++) {
                u32 bbh[2] = {bh0[ni], bh1[ni]};
                u32 bbl[2] = {bl0[ni], bl1[ni]};
                mma_f16(c[mi][ni], ah[mi], bbh);
                mma_f16(c[mi][ni], ah[mi], bbl);
            }
        __syncthreads();
    }
    #pragma unroll
    for (int mi = 0; mi < 2; mi++) {
        int r = row0 + wm * 32 + mi * 16 + g;
        #pragma unroll
        for (int ni = 0; ni < 4; ni++) {
            int cc = col0 + wn * 32 + ni * 8 + tg * 2;
            if (r < M)
                *(__half2*)(C + (size_t)r * ldc + cc) =
                    __floats2half2_rn(c[mi][ni][0], c[mi][ni][1]);
            if (r + 8 < M)
                *(__half2*)(C + (size_t)(r + 8) * ldc + cc) =
                    __floats2half2_rn(c[mi][ni][2], c[mi][ni][3]);
        }
    }
}

// ---------------- aggregation (fp16 gathers, unroll x4) ----------------
__global__ __launch_bounds__(256) void k_agg1(
    const float* __restrict__ b1A, const float* __restrict__ b1B,
    const float* __restrict__ b1C, const float* __restrict__ b1D)
{
    int v = blockIdx.x * 2 + (threadIdx.x >> 7);
    int wid = (threadIdx.x >> 5) & 3, lane = threadIdx.x & 31;
    if (v >= NN) return;
    int beg = d_rowptr[v], end = d_rowptr[v + 1];
    const float* nrm = (const float*)d_csr_nrm4;
    float4 acc = make_float4(0.f, 0.f, 0.f, 0.f);
    int p = beg;
    for (; p + 4 <= end; p += 4) {
        int s0 = d_csr_src[p],     s1 = d_csr_src[p + 1];
        int s2 = d_csr_src[p + 2], s3 = d_csr_src[p + 3];
        float n0 = __ldg(nrm + p * 4 + wid);
        float n1 = __ldg(nrm + (p + 1) * 4 + wid);
        float n2 = __ldg(nrm + (p + 2) * 4 + wid);
        float n3 = __ldg(nrm + (p + 3) * 4 + wid);
        fma_h4(acc, d_h1lin + (size_t)s0 * 512 + wid * 128 + lane * 4, n0);
        fma_h4(acc, d_h1lin + (size_t)s1 * 512 + wid * 128 + lane * 4, n1);
        fma_h4(acc, d_h1lin + (size_t)s2 * 512 + wid * 128 + lane * 4, n2);
        fma_h4(acc, d_h1lin + (size_t)s3 * 512 + wid * 128 + lane * 4, n3);
    }
    for (; p < end; ++p) {
        int s0 = d_csr_src[p];
        float n0 = __ldg(nrm + p * 4 + wid);
        fma_h4(acc, d_h1lin + (size_t)s0 * 512 + wid * 128 + lane * 4, n0);
    }
    float dv = d_dis4[wid * NN + v];
    fma_h4(acc, d_h1lin + (size_t)v * 512 + wid * 128 + lane * 4, dv * dv);
    const float* bp = (wid == 0) ? b1A : (wid == 1) ? b1B : (wid == 2) ? b1C : b1D;
    float4 bb = *(const float4*)(bp + lane * 4);
    float4 o;
    o.x = fmaxf(acc.x + bb.x, 0.f); o.y = fmaxf(acc.y + bb.y, 0.f);
    o.z = fmaxf(acc.z + bb.z, 0.f); o.w = fmaxf(acc.w + bb.w, 0.f);
    st_h4(d_xcat + (size_t)v * 512 + wid * 128 + lane * 4, o);
}

__global__ __launch_bounds__(256) void k_agg2(const float* __restrict__ b2) {
    int v = blockIdx.x * 4 + (threadIdx.x >> 6);
    int t6 = threadIdx.x & 63;
    if (v >= NN) return;
    int beg = d_rowptr[v], end = d_rowptr[v + 1];
    float4 acc = make_float4(0.f, 0.f, 0.f, 0.f);
    int p = beg;
    for (; p + 4 <= end; p += 4) {
        int s0 = d_csr_src[p],     s1 = d_csr_src[p + 1];
        int s2 = d_csr_src[p + 2], s3 = d_csr_src[p + 3];
        float n0 = __ldg(d_csr_nrm1 + p),     n1 = __ldg(d_csr_nrm1 + p + 1);
        float n2 = __ldg(d_csr_nrm1 + p + 2), n3 = __ldg(d_csr_nrm1 + p + 3);
        fma_h4(acc, d_h2lin + (size_t)s0 * 256 + t6 * 4, n0);
        fma_h4(acc, d_h2lin + (size_t)s1 * 256 + t6 * 4, n1);
        fma_h4(acc, d_h2lin + (size_t)s2 * 256 + t6 * 4, n2);
        fma_h4(acc, d_h2lin + (size_t)s3 * 256 + t6 * 4, n3);
    }
    for (; p < end; ++p) {
        int s0 = d_csr_src[p];
        float n0 = __ldg(d_csr_nrm1 + p);
        fma_h4(acc, d_h2lin + (size_t)s0 * 256 + t6 * 4, n0);
    }
    float dv = d_dis1[v];
    fma_h4(acc, d_h2lin + (size_t)v * 256 + t6 * 4, dv * dv);
    float4 bb = *(const float4*)(b2 + t6 * 4);
    float4 o;
    o.x = fmaxf(acc.x + bb.x, 0.f); o.y = fmaxf(acc.y + bb.y, 0.f);
    o.z = fmaxf(acc.z + bb.z, 0.f); o.w = fmaxf(acc.w + bb.w, 0.f);
    st_h4(d_h2 + (size_t)v * 256 + t6 * 4, o);
}

__global__ __launch_bounds__(256) void k_agg3(const float* __restrict__ b3) {
    int v = blockIdx.x * 8 + (threadIdx.x >> 5);
    int lane = threadIdx.x & 31;
    if (v >= NN) return;
    int beg = d_rowptr[v], end = d_rowptr[v + 1];
    float4 acc = make_float4(0.f, 0.f, 0.f, 0.f);
    int p = beg;
    for (; p + 4 <= end; p += 4) {
        int s0 = d_csr_src[p],     s1 = d_csr_src[p + 1];
        int s2 = d_csr_src[p + 2], s3 = d_csr_src[p + 3];
        float n0 = __ldg(d_csr_nrm1 + p),     n1 = __ldg(d_csr_nrm1 + p + 1);
        float n2 = __ldg(d_csr_nrm1 + p + 2), n3 = __ldg(d_csr_nrm1 + p + 3);
        fma_h4(acc, d_h3lin + (size_t)s0 * 128 + lane * 4, n0);
        fma_h4(acc, d_h3lin + (size_t)s1 * 128 + lane * 4, n1);
        fma_h4(acc, d_h3lin + (size_t)s2 * 128 + lane * 4, n2);
        fma_h4(acc, d_h3lin + (size_t)s3 * 128 + lane * 4, n3);
    }
    for (; p < end; ++p) {
        int s0 = d_csr_src[p];
        float n0 = __ldg(d_csr_nrm1 + p);
        fma_h4(acc, d_h3lin + (size_t)s0 * 128 + lane * 4, n0);
    }
    float dv = d_dis1[v];
    fma_h4(acc, d_h3lin + (size_t)v * 128 + lane * 4, dv * dv);
    float4 bb = *(const float4*)(b3 + lane * 4);
    float4 o;
    o.x = acc.x + bb.x; o.y = acc.y + bb.y;
    o.z = acc.z + bb.z; o.w = acc.w + bb.w;
    *(float4*)(d_h3 + (size_t)v * 128 + lane * 4) = o;
}

// ---------------- pooling + head ----------------
__global__ void k_bounds(const int* __restrict__ batch) {
    int i = blockIdx.x * blockDim.x + threadIdx.x;
    if (i >= NN) return;
    int b = batch[i];
    if (i == 0) {
        for (int g = 0; g <= b; ++g) d_gstart[g] = 0;
    } else {
        int pb = batch[i - 1];
        if (pb != b)
            for (int g = pb + 1; g <= b; ++g) d_gstart[g] = i;
    }
    if (i == NN - 1) {
        for (int g = b + 1; g <= NG; ++g) d_gstart[g] = NN;
    }
}

__global__ __launch_bounds__(128) void k_pool() {
    __shared__ float4 ssum[4][32], smax[4][32];
    int g = blockIdx.x;
    int wid = threadIdx.x >> 5, lane = threadIdx.x & 31;
    int beg = d_gstart[g], end = d_gstart[g + 1];
    int cnt = end - beg;
    float4 s = make_float4(0.f, 0.f, 0.f, 0.f);
    float4 m = make_float4(-INFINITY, -INFINITY, -INFINITY, -INFINITY);
    for (int i = beg + wid; i < end; i += 4) {
        float4 v = *(const float4*)(d_h3 + (size_t)i * 128 + lane * 4);
        s.x += v.x; s.y += v.y; s.z += v.z; s.w += v.w;
        m.x = fmaxf(m.x, v.x); m.y = fmaxf(m.y, v.y);
        m.z = fmaxf(m.z, v.z); m.w = fmaxf(m.w, v.w);
    }
    ssum[wid][lane] = s; smax[wid][lane] = m;
    __syncthreads();
    if (wid == 0) {
        #pragma unroll
        for (int w = 1; w < 4; ++w) {
            float4 s2 = ssum[w][lane], m2 = smax[w][lane];
            s.x += s2.x; s.y += s2.y; s.z += s2.z; s.w += s2.w;
            m.x = fmaxf(m.x, m2.x); m.y = fmaxf(m.y, m2.y);
            m.z = fmaxf(m.z, m2.z); m.w = fmaxf(m.w, m2.w);
        }
        float inv = 1.0f / fmaxf((float)cnt, 1.0f);
        float4 mean = make_float4(s.x * inv, s.y * inv, s.z * inv, s.w * inv);
        if (cnt == 0) m = make_float4(0.f, 0.f, 0.f, 0.f);
        *(float4*)(d_gmat + g * 256 + lane * 4) = mean;
        *(float4*)(d_gmat + g * 256 + 128 + lane * 4) = m;
    }
}

__global__ void k_mlp(const float* __restrict__ Wm1, const float* __restrict__ bm1,
                      const float* __restrict__ Wm2, const float* __restrict__ bm2,
                      float* __restrict__ out) {
    int g = threadIdx.x;
    if (g >= NG) return;
    const float* gv = d_gmat + g * 256;
    float hid[8];
    #pragma unroll
    for (int j = 0; j < 8; ++j) {
        float s = bm1[j];
        for (int k = 0; k < 256; ++k) s += gv[k] * Wm1[k * 8 + j];
        hid[j] = fmaxf(s, 0.f);
    }
    #pragma unroll
    for (int c = 0; c < 2; ++c) {
        float o = bm2[c];
        #pragma unroll
        for (int j = 0; j < 8; ++j) o += hid[j] * Wm2[j * 2 + c];
        out[g * 2 + c] = o;
    }
}

// ---------------- launch ----------------
extern "C" void kernel_launch(void* const* d_in, const int* in_sizes, int n_in,
                              void* d_out, int out_size) {
    const float* x   = (const float*)d_in[0];
    const int*   ei  = (const int*)d_in[1];
    const float* ea  = (const float*)d_in[2];
    const int*   bat = (const int*)d_in[3];
    const float* W1A = (const float*)d_in[4];  const float* b1A = (const float*)d_in[5];
    const float* W1B = (const float*)d_in[6];  const float* b1B = (const float*)d_in[7];
    const float* W1C = (const float*)d_in[8];  const float* b1C = (const float*)d_in[9];
    const float* W1D = (const float*)d_in[10]; const float* b1D = (const float*)d_in[11];
    const float* W2  = (const float*)d_in[12]; const float* b2  = (const float*)d_in[13];
    const float* W3  = (const float*)d_in[14]; const float* b3  = (const float*)d_in[15];
    const float* Wm1 = (const float*)d_in[16]; const float* bm1 = (const float*)d_in[17];
    const float* Wm2 = (const float*)d_in[18]; const float* bm2 = (const float*)d_in[19];
    float* out = (float*)d_out;

    __half *xh, *h1lin, *xcat, *h2lin, *h2, *h3lin;
    unsigned short *wc_hi, *wc_lo, *w2_hi, *w2_lo, *w3_hi, *w3_lo;
    cudaGetSymbolAddress((void**)&xh,    d_xh);
    cudaGetSymbolAddress((void**)&h1lin, d_h1lin);
    cudaGetSymbolAddress((void**)&xcat,  d_xcat);
    cudaGetSymbolAddress((void**)&h2lin, d_h2lin);
    cudaGetSymbolAddress((void**)&h2,    d_h2);
    cudaGetSymbolAddress((void**)&h3lin, d_h3lin);
    cudaGetSymbolAddress((void**)&wc_hi, d_wc_hi);
    cudaGetSymbolAddress((void**)&wc_lo, d_wc_lo);
    cudaGetSymbolAddress((void**)&w2_hi, d_w2_hi);
    cudaGetSymbolAddress((void**)&w2_lo, d_w2_lo);
    cudaGetSymbolAddress((void**)&w3_hi, d_w3_hi);
    cudaGetSymbolAddress((void**)&w3_lo, d_w3_lo);

    cudaStream_t s1;
    cudaEvent_t ev0, ev1;
    cudaStreamCreateWithFlags(&s1, cudaStreamNonBlocking);
    cudaEventCreateWithFlags(&ev0, cudaEventDisableTiming);
    cudaEventCreateWithFlags(&ev1, cudaEventDisableTiming);

    const int TB = 256;
    k_init<<<196 + 896, 256>>>(W1A, W1B, W1C, W1D, W2, W3);

    cudaEventRecord(ev0, 0);
    cudaStreamWaitEvent(s1, ev0, 0);
    k_degree<<<(NE + TB - 1) / TB, TB, 0, s1>>>(ei, ea);
    k_rsqrt <<<(5 * NN + TB - 1) / TB, TB, 0, s1>>>();
    k_bsum  <<<196, 256, 0, s1>>>();
    k_bscan <<<1, 256, 0, s1>>>();
    k_scan3 <<<196, 256, 0, s1>>>();
    k_scatter<<<(NE + TB - 1) / TB, TB, 0, s1>>>(ei, ea);
    k_bounds<<<(NN + TB - 1) / TB, TB, 0, s1>>>(bat);
    cudaEventRecord(ev1, s1);

    k_x2h<<<(NN * 16 + 255) / 256, 256>>>(x);
    mma_gemm<<<dim3(4, 391), 512>>>(xh, wc_hi, wc_lo, h1lin, NN, 128, 512);

    cudaStreamWaitEvent(0, ev1, 0);

    k_agg1<<<(NN + 1) / 2, 256>>>(b1A, b1B, b1C, b1D);

    mma_gemm<<<dim3(2, 391), 512>>>(xcat, w2_hi, w2_lo, h2lin, NN, 512, 256);
    k_agg2<<<(NN + 3) / 4, 256>>>(b2);

    mma_gemm<<<dim3(1, 391), 512>>>(h2, w3_hi, w3_lo, h3lin, NN, 256, 128);
    k_agg3<<<(NN + 7) / 8, 256>>>(b3);

    k_pool<<<NG, 128>>>();
    k_mlp<<<1, NG>>>(Wm1, bm1, Wm2, bm2, out);
}

// round 13
// speedup vs baseline: 1.0903x; 1.0903x over previous
#include <cuda_runtime.h>
#include <cuda_fp16.h>
#include <math.h>
#include <cstdint>

#define NN 50000
#define NE 600000
#define NG 64

typedef unsigned long long u64;
typedef unsigned int u32;

// ---------------- scratch (device globals; allocation-free) ----------------
__device__ __half d_xh   [(size_t)NN * 128];
__device__ __half d_h1lin[(size_t)NN * 512];
__device__ __half d_xcat [(size_t)NN * 512];
__device__ __half d_h2lin[(size_t)NN * 256];
__device__ __half d_h2   [(size_t)NN * 256];
__device__ __half d_h3lin[(size_t)NN * 128];
__device__ float  d_h3   [(size_t)NN * 128];
__device__ unsigned short d_wc_hi[512 * 128], d_wc_lo[512 * 128];
__device__ unsigned short d_w2_hi[256 * 512], d_w2_lo[256 * 512];
__device__ unsigned short d_w3_hi[128 * 256], d_w3_lo[128 * 256];
__device__ float d_dis4[4 * NN];
__device__ float d_dis1[NN];
__device__ int   d_cnt[NN];
__device__ int   d_rowptr[NN + 1];
__device__ int   d_wrptr[NN];
__device__ int   d_csr_src[NE];
__device__ float4 d_csr_nrm4[NE];
__device__ float  d_csr_nrm1[NE];
__device__ int   d_bsum[256];
__device__ int   d_boff[256];
__device__ int   d_gstart[NG + 1];
__device__ float d_gmat[NG * 256];

__device__ __forceinline__ u32 smem_u32(const void* p) {
    u32 a;
    asm("{ .reg .u64 t; cvta.to.shared.u64 t, %1; cvt.u32.u64 %0, t; }" : "=r"(a) : "l"(p));
    return a;
}

__device__ __forceinline__ void splitf16(float a, unsigned short& h, unsigned short& l) {
    __half hh = __float2half_rn(a);
    float r = a - __half2float(hh);
    __half ll = __float2half_rn(r);
    h = *reinterpret_cast<unsigned short*>(&hh);
    l = *reinterpret_cast<unsigned short*>(&ll);
}

__device__ __forceinline__ void mma_f16(float* d, const u32* a, const u32* b) {
    asm volatile(
        "mma.sync.aligned.m16n8k16.row.col.f32.f16.f16.f32 "
        "{%0,%1,%2,%3}, {%4,%5,%6,%7}, {%8,%9}, {%0,%1,%2,%3};"
        : "+f"(d[0]), "+f"(d[1]), "+f"(d[2]), "+f"(d[3])
        : "r"(a[0]), "r"(a[1]), "r"(a[2]), "r"(a[3]), "r"(b[0]), "r"(b[1]));
}

__device__ __forceinline__ void ldm4(u32* d, u32 addr) {
    asm volatile("ldmatrix.sync.aligned.m8n8.x4.shared.b16 {%0,%1,%2,%3}, [%4];"
        : "=r"(d[0]), "=r"(d[1]), "=r"(d[2]), "=r"(d[3]) : "r"(addr));
}

__device__ __forceinline__ void fma_h4(float4& acc, const __half* p, float n) {
    uint2 raw = *(const uint2*)p;
    __half2 p0 = *reinterpret_cast<__half2*>(&raw.x);
    __half2 p1 = *reinterpret_cast<__half2*>(&raw.y);
    float2 f0 = __half22float2(p0);
    float2 f1 = __half22float2(p1);
    acc.x += f0.x * n; acc.y += f0.y * n;
    acc.z += f1.x * n; acc.w += f1.y * n;
}

__device__ __forceinline__ void st_h4(__half* p, float4 o) {
    union { __half2 h2[2]; uint2 u; } cv;
    cv.h2[0] = __floats2half2_rn(o.x, o.y);
    cv.h2[1] = __floats2half2_rn(o.z, o.w);
    *(uint2*)p = cv.u;
}

// ---------------- setup ----------------
__global__ void k_init(const float* __restrict__ WA, const float* __restrict__ WB,
                       const float* __restrict__ WC, const float* __restrict__ WD,
                       const float* __restrict__ W2, const float* __restrict__ W3) {
    int b = blockIdx.x;
    if (b < 196) {
        int v = b * 256 + threadIdx.x;
        if (v < NN) {
            d_dis4[v] = 1.0f; d_dis4[NN + v] = 1.0f;
            d_dis4[2 * NN + v] = 1.0f; d_dis4[3 * NN + v] = 1.0f;
            d_dis1[v] = 1.0f;
        }
        return;
    }
    int i = (b - 196) * 256 + threadIdx.x;
    float v; unsigned short h, l;
    if (i < 65536) {
        int n = i >> 7, kk = i & 127;
        int conv = n >> 7, c = n & 127;
        const float* W = (conv == 0) ? WA : (conv == 1) ? WB : (conv == 2) ? WC : WD;
        v = W[kk * 128 + c];
        splitf16(v, h, l);
        d_wc_hi[i] = h; d_wc_lo[i] = l;
    } else if (i < 65536 + 131072) {
        int j = i - 65536;
        int n = j >> 9, kk = j & 511;
        v = W2[kk * 256 + n];
        splitf16(v, h, l);
        d_w2_hi[j] = h; d_w2_lo[j] = l;
    } else {
        int j = i - 196608;
        int n = j >> 8, kk = j & 255;
        v = W3[kk * 128 + n];
        splitf16(v, h, l);
        d_w3_hi[j] = h; d_w3_lo[j] = l;
    }
}

__global__ void k_x2h(const float* __restrict__ x) {
    int i = blockIdx.x * blockDim.x + threadIdx.x;
    if (i >= NN * 16) return;
    float4 f0 = *(const float4*)(x + (size_t)i * 8);
    float4 f1 = *(const float4*)(x + (size_t)i * 8 + 4);
    union { __half2 h2[4]; uint4 u; } cv;
    cv.h2[0] = __floats2half2_rn(f0.x, f0.y);
    cv.h2[1] = __floats2half2_rn(f0.z, f0.w);
    cv.h2[2] = __floats2half2_rn(f1.x, f1.y);
    cv.h2[3] = __floats2half2_rn(f1.z, f1.w);
    *(uint4*)(d_xh + (size_t)i * 8) = cv.u;
}

__global__ void k_degree(const int* __restrict__ ei, const float* __restrict__ ea) {
    int e = blockIdx.x * blockDim.x + threadIdx.x;
    if (e >= NE) return;
    int dst = ei[NE + e];
    float4 w = __ldg((const float4*)ea + e);
    atomicAdd(&d_dis4[dst], w.x);
    atomicAdd(&d_dis4[NN + dst], w.y);
    atomicAdd(&d_dis4[2 * NN + dst], w.z);
    atomicAdd(&d_dis4[3 * NN + dst], w.w);
    atomicAdd(&d_dis1[dst], 1.0f);
}

__global__ void k_rsqrt() {
    int v = blockIdx.x * blockDim.x + threadIdx.x;
    if (v < 4 * NN) {
        d_dis4[v] = rsqrtf(d_dis4[v]);
    } else if (v < 5 * NN) {
        int u = v - 4 * NN;
        float deg = d_dis1[u];
        d_cnt[u] = (int)(deg - 0.5f);
        d_dis1[u] = rsqrtf(deg);
    }
}

// ---------------- 3-phase grid scan ----------------
__global__ void k_bsum() {
    __shared__ int ws[8];
    int idx = blockIdx.x * 256 + threadIdx.x;
    int v = (idx < NN) ? d_cnt[idx] : 0;
    int lane = threadIdx.x & 31, wid = threadIdx.x >> 5;
    int s = v;
    #pragma unroll
    for (int o = 16; o > 0; o >>= 1) s += __shfl_down_sync(0xffffffffu, s, o);
    if (lane == 0) ws[wid] = s;
    __syncthreads();
    if (wid == 0) {
        int t = (lane < 8) ? ws[lane] : 0;
        #pragma unroll
        for (int o = 4; o > 0; o >>= 1) t += __shfl_down_sync(0xffffffffu, t, o);
        if (lane == 0) d_bsum[blockIdx.x] = t;
    }
}

__global__ void k_bscan() {
    __shared__ int ws[8];
    int t = threadIdx.x;
    int lane = t & 31, wid = t >> 5;
    int v = (t < 196) ? d_bsum[t] : 0;
    int x = v;
    #pragma unroll
    for (int o = 1; o < 32; o <<= 1) {
        int y = __shfl_up_sync(0xffffffffu, x, o);
        if (lane >= o) x += y;
    }
    if (lane == 31) ws[wid] = x;
    __syncthreads();
    if (wid == 0 && lane < 8) {
        int s = ws[lane];
        #pragma unroll
        for (int o = 1; o < 8; o <<= 1) {
            int y = __shfl_up_sync(0xffu, s, o);
            if (lane >= o) s += y;
        }
        ws[lane] = s;
    }
    __syncthreads();
    int excl = x - v + (wid > 0 ? ws[wid - 1] : 0);
    if (t < 196) d_boff[t] = excl;
    if (t == 0) d_rowptr[NN] = NE;
}

__global__ void k_scan3() {
    __shared__ int ws[8];
    int idx = blockIdx.x * 256 + threadIdx.x;
    int t = threadIdx.x;
    int lane = t & 31, wid = t >> 5;
    int v = (idx < NN) ? d_cnt[idx] : 0;
    int x = v;
    #pragma unroll
    for (int o = 1; o < 32; o <<= 1) {
        int y = __shfl_up_sync(0xffffffffu, x, o);
        if (lane >= o) x += y;
    }
    if (lane == 31) ws[wid] = x;
    __syncthreads();
    if (wid == 0 && lane < 8) {
        int s = ws[lane];
        #pragma unroll
        for (int o = 1; o < 8; o <<= 1) {
            int y = __shfl_up_sync(0xffu, s, o);
            if (lane >= o) s += y;
        }
        ws[lane] = s;
    }
    __syncthreads();
    int excl = x - v + (wid > 0 ? ws[wid - 1] : 0) + d_boff[blockIdx.x];
    if (idx < NN) { d_rowptr[idx] = excl; d_wrptr[idx] = excl; }
}

__global__ void k_scatter(const int* __restrict__ ei, const float* __restrict__ ea) {
    int e = blockIdx.x * blockDim.x + threadIdx.x;
    if (e >= NE) return;
    int src = ei[e];
    int dst = ei[NE + e];
    float4 w = __ldg((const float4*)ea + e);
    int pos = atomicAdd(&d_wrptr[dst], 1);
    float4 n4;
    n4.x = d_dis4[src] * w.x * d_dis4[dst];
    n4.y = d_dis4[NN + src] * w.y * d_dis4[NN + dst];
    n4.z = d_dis4[2 * NN + src] * w.z * d_dis4[2 * NN + dst];
    n4.w = d_dis4[3 * NN + src] * w.w * d_dis4[3 * NN + dst];
    d_csr_src[pos] = src;
    d_csr_nrm4[pos] = n4;
    d_csr_nrm1[pos] = d_dis1[src] * d_dis1[dst];
}

// ============ fp16 2-term GEMM (R10 shape): C = A(fp16) @ (Bhi+Blo)^T ============
#define KT 32
#define ASTR 40

__global__ __launch_bounds__(512, 1) void mma_gemm(
    const __half* __restrict__ A, const unsigned short* __restrict__ Bhi,
    const unsigned short* __restrict__ Blo, __half* __restrict__ C,
    int M, int K, int ldc)
{
    __shared__ unsigned short sA [128 * ASTR];
    __shared__ unsigned short sBh[128 * ASTR], sBl[128 * ASTR];
    int tid = threadIdx.x;
    int wid = tid >> 5, lane = tid & 31;
    int g = lane >> 2, tg = lane & 3;
    int wm = wid >> 2, wn = wid & 3;
    int row0 = blockIdx.y * 128, col0 = blockIdx.x * 128;

    u32 bA = smem_u32(sA);
    u32 bBh = smem_u32(sBh), bBl = smem_u32(sBl);
    u32 aOff = (u32)(((wm * 32 + (lane & 15)) * ASTR + ((lane >> 4) << 3)) * 2);
    u32 bOff = (u32)(((wn * 32 + lane) * ASTR) * 2);

    float c[2][4][4];
    #pragma unroll
    for (int mi = 0; mi < 2; mi++)
        #pragma unroll
        for (int ni = 0; ni < 4; ni++)
            #pragma unroll
            for (int q = 0; q < 4; q++) c[mi][ni][q] = 0.f;

    int rowA = tid >> 2, segA = tid & 3;
    for (int kc = 0; kc < K; kc += KT) {
        {
            int gr = row0 + rowA;
            uint4 va = make_uint4(0u, 0u, 0u, 0u);
            if (gr < M) va = *(const uint4*)(A + (size_t)gr * K + kc + segA * 8);
            *(uint4*)&sA[rowA * ASTR + segA * 8] = va;
            size_t gi = (size_t)(col0 + rowA) * K + kc + segA * 8;
            *(uint4*)&sBh[rowA * ASTR + segA * 8] = *(const uint4*)(Bhi + gi);
            *(uint4*)&sBl[rowA * ASTR + segA * 8] = *(const uint4*)(Blo + gi);
        }
        __syncthreads();
        #pragma unroll
        for (int ks = 0; ks < KT; ks += 16) {
            u32 ah[2][4];
            u32 bh0[4], bh1[4], bl0[4], bl1[4];
            u32 ksb = (u32)(ks * 2);
            ldm4(ah[0], bA + aOff + ksb);
            ldm4(ah[1], bA + aOff + ksb + 16 * ASTR * 2);
            ldm4(bh0, bBh + bOff + ksb);
            ldm4(bh1, bBh + bOff + ksb + 16);
            ldm4(bl0, bBl + bOff + ksb);
            ldm4(bl1, bBl + bOff + ksb + 16);
            #pragma unroll
            for (int mi = 0; mi < 2; mi++)
                #pragma unroll
                for (int ni = 0; ni < 4; ni++) {
                    u32 bbh[2] = {bh0[ni], bh1[ni]};
                    u32 bbl[2] = {bl0[ni], bl1[ni]};
                    mma_f16(c[mi][ni], ah[mi], bbh);
                    mma_f16(c[mi][ni], ah[mi], bbl);
                }
        }
        __syncthreads();
    }
    #pragma unroll
    for (int mi = 0; mi < 2; mi++) {
        int r = row0 + wm * 32 + mi * 16 + g;
        #pragma unroll
        for (int ni = 0; ni < 4; ni++) {
            int cc = col0 + wn * 32 + ni * 8 + tg * 2;
            if (r < M)
                *(__half2*)(C + (size_t)r * ldc + cc) =
                    __floats2half2_rn(c[mi][ni][0], c[mi][ni][1]);
            if (r + 8 < M)
                *(__half2*)(C + (size_t)(r + 8) * ldc + cc) =
                    __floats2half2_rn(c[mi][ni][2], c[mi][ni][3]);
        }
    }
}

// ---------------- aggregation (fp16 gathers, unroll x4) ----------------
__global__ __launch_bounds__(256) void k_agg1(
    const float* __restrict__ b1A, const float* __restrict__ b1B,
    const float* __restrict__ b1C, const float* __restrict__ b1D)
{
    int v = blockIdx.x * 2 + (threadIdx.x >> 7);
    int wid = (threadIdx.x >> 5) & 3, lane = threadIdx.x & 31;
    if (v >= NN) return;
    int beg = d_rowptr[v], end = d_rowptr[v + 1];
    const float* nrm = (const float*)d_csr_nrm4;
    float4 acc = make_float4(0.f, 0.f, 0.f, 0.f);
    int p = beg;
    for (; p + 4 <= end; p += 4) {
        int s0 = d_csr_src[p],     s1 = d_csr_src[p + 1];
        int s2 = d_csr_src[p + 2], s3 = d_csr_src[p + 3];
        float n0 = __ldg(nrm + p * 4 + wid);
        float n1 = __ldg(nrm + (p + 1) * 4 + wid);
        float n2 = __ldg(nrm + (p + 2) * 4 + wid);
        float n3 = __ldg(nrm + (p + 3) * 4 + wid);
        fma_h4(acc, d_h1lin + (size_t)s0 * 512 + wid * 128 + lane * 4, n0);
        fma_h4(acc, d_h1lin + (size_t)s1 * 512 + wid * 128 + lane * 4, n1);
        fma_h4(acc, d_h1lin + (size_t)s2 * 512 + wid * 128 + lane * 4, n2);
        fma_h4(acc, d_h1lin + (size_t)s3 * 512 + wid * 128 + lane * 4, n3);
    }
    for (; p < end; ++p) {
        int s0 = d_csr_src[p];
        float n0 = __ldg(nrm + p * 4 + wid);
        fma_h4(acc, d_h1lin + (size_t)s0 * 512 + wid * 128 + lane * 4, n0);
    }
    float dv = d_dis4[wid * NN + v];
    fma_h4(acc, d_h1lin + (size_t)v * 512 + wid * 128 + lane * 4, dv * dv);
    const float* bp = (wid == 0) ? b1A : (wid == 1) ? b1B : (wid == 2) ? b1C : b1D;
    float4 bb = *(const float4*)(bp + lane * 4);
    float4 o;
    o.x = fmaxf(acc.x + bb.x, 0.f); o.y = fmaxf(acc.y + bb.y, 0.f);
    o.z = fmaxf(acc.z + bb.z, 0.f); o.w = fmaxf(acc.w + bb.w, 0.f);
    st_h4(d_xcat + (size_t)v * 512 + wid * 128 + lane * 4, o);
}

__global__ __launch_bounds__(256) void k_agg2(const float* __restrict__ b2) {
    int v = blockIdx.x * 4 + (threadIdx.x >> 6);
    int t6 = threadIdx.x & 63;
    if (v >= NN) return;
    int beg = d_rowptr[v], end = d_rowptr[v + 1];
    float4 acc = make_float4(0.f, 0.f, 0.f, 0.f);
    int p = beg;
    for (; p + 4 <= end; p += 4) {
        int s0 = d_csr_src[p],     s1 = d_csr_src[p + 1];
        int s2 = d_csr_src[p + 2], s3 = d_csr_src[p + 3];
        float n0 = __ldg(d_csr_nrm1 + p),     n1 = __ldg(d_csr_nrm1 + p + 1);
        float n2 = __ldg(d_csr_nrm1 + p + 2), n3 = __ldg(d_csr_nrm1 + p + 3);
        fma_h4(acc, d_h2lin + (size_t)s0 * 256 + t6 * 4, n0);
        fma_h4(acc, d_h2lin + (size_t)s1 * 256 + t6 * 4, n1);
        fma_h4(acc, d_h2lin + (size_t)s2 * 256 + t6 * 4, n2);
        fma_h4(acc, d_h2lin + (size_t)s3 * 256 + t6 * 4, n3);
    }
    for (; p < end; ++p) {
        int s0 = d_csr_src[p];
        float n0 = __ldg(d_csr_nrm1 + p);
        fma_h4(acc, d_h2lin + (size_t)s0 * 256 + t6 * 4, n0);
    }
    float dv = d_dis1[v];
    fma_h4(acc, d_h2lin + (size_t)v * 256 + t6 * 4, dv * dv);
    float4 bb = *(const float4*)(b2 + t6 * 4);
    float4 o;
    o.x = fmaxf(acc.x + bb.x, 0.f); o.y = fmaxf(acc.y + bb.y, 0.f);
    o.z = fmaxf(acc.z + bb.z, 0.f); o.w = fmaxf(acc.w + bb.w, 0.f);
    st_h4(d_h2 + (size_t)v * 256 + t6 * 4, o);
}

__global__ __launch_bounds__(256) void k_agg3(const float* __restrict__ b3) {
    int v = blockIdx.x * 8 + (threadIdx.x >> 5);
    int lane = threadIdx.x & 31;
    if (v >= NN) return;
    int beg = d_rowptr[v], end = d_rowptr[v + 1];
    float4 acc = make_float4(0.f, 0.f, 0.f, 0.f);
    int p = beg;
    for (; p + 4 <= end; p += 4) {
        int s0 = d_csr_src[p],     s1 = d_csr_src[p + 1];
        int s2 = d_csr_src[p + 2], s3 = d_csr_src[p + 3];
        float n0 = __ldg(d_csr_nrm1 + p),     n1 = __ldg(d_csr_nrm1 + p + 1);
        float n2 = __ldg(d_csr_nrm1 + p + 2), n3 = __ldg(d_csr_nrm1 + p + 3);
        fma_h4(acc, d_h3lin + (size_t)s0 * 128 + lane * 4, n0);
        fma_h4(acc, d_h3lin + (size_t)s1 * 128 + lane * 4, n1);
        fma_h4(acc, d_h3lin + (size_t)s2 * 128 + lane * 4, n2);
        fma_h4(acc, d_h3lin + (size_t)s3 * 128 + lane * 4, n3);
    }
    for (; p < end; ++p) {
        int s0 = d_csr_src[p];
        float n0 = __ldg(d_csr_nrm1 + p);
        fma_h4(acc, d_h3lin + (size_t)s0 * 128 + lane * 4, n0);
    }
    float dv = d_dis1[v];
    fma_h4(acc, d_h3lin + (size_t)v * 128 + lane * 4, dv * dv);
    float4 bb = *(const float4*)(b3 + lane * 4);
    float4 o;
    o.x = acc.x + bb.x; o.y = acc.y + bb.y;
    o.z = acc.z + bb.z; o.w = acc.w + bb.w;
    *(float4*)(d_h3 + (size_t)v * 128 + lane * 4) = o;
}

// ---------------- pooling + head ----------------
__global__ void k_bounds(const int* __restrict__ batch) {
    int i = blockIdx.x * blockDim.x + threadIdx.x;
    if (i >= NN) return;
    int b = batch[i];
    if (i == 0) {
        for (int g = 0; g <= b; ++g) d_gstart[g] = 0;
    } else {
        int pb = batch[i - 1];
        if (pb != b)
            for (int g = pb + 1; g <= b; ++g) d_gstart[g] = i;
    }
    if (i == NN - 1) {
        for (int g = b + 1; g <= NG; ++g) d_gstart[g] = NN;
    }
}

__global__ __launch_bounds__(128) void k_pool() {
    __shared__ float4 ssum[4][32], smax[4][32];
    int g = blockIdx.x;
    int wid = threadIdx.x >> 5, lane = threadIdx.x & 31;
    int beg = d_gstart[g], end = d_gstart[g + 1];
    int cnt = end - beg;
    float4 s = make_float4(0.f, 0.f, 0.f, 0.f);
    float4 m = make_float4(-INFINITY, -INFINITY, -INFINITY, -INFINITY);
    for (int i = beg + wid; i < end; i += 4) {
        float4 v = *(const float4*)(d_h3 + (size_t)i * 128 + lane * 4);
        s.x += v.x; s.y += v.y; s.z += v.z; s.w += v.w;
        m.x = fmaxf(m.x, v.x); m.y = fmaxf(m.y, v.y);
        m.z = fmaxf(m.z, v.z); m.w = fmaxf(m.w, v.w);
    }
    ssum[wid][lane] = s; smax[wid][lane] = m;
    __syncthreads();
    if (wid == 0) {
        #pragma unroll
        for (int w = 1; w < 4; ++w) {
            float4 s2 = ssum[w][lane], m2 = smax[w][lane];
            s.x += s2.x; s.y += s2.y; s.z += s2.z; s.w += s2.w;
            m.x = fmaxf(m.x, m2.x); m.y = fmaxf(m.y, m2.y);
            m.z = fmaxf(m.z, m2.z); m.w = fmaxf(m.w, m2.w);
        }
        float inv = 1.0f / fmaxf((float)cnt, 1.0f);
        float4 mean = make_float4(s.x * inv, s.y * inv, s.z * inv, s.w * inv);
        if (cnt == 0) m = make_float4(0.f, 0.f, 0.f, 0.f);
        *(float4*)(d_gmat + g * 256 + lane * 4) = mean;
        *(float4*)(d_gmat + g * 256 + 128 + lane * 4) = m;
    }
}

__global__ void k_mlp(const float* __restrict__ Wm1, const float* __restrict__ bm1,
                      const float* __restrict__ Wm2, const float* __restrict__ bm2,
                      float* __restrict__ out) {
    int g = threadIdx.x;
    if (g >= NG) return;
    const float* gv = d_gmat + g * 256;
    float hid[8];
    #pragma unroll
    for (int j = 0; j < 8; ++j) {
        float s = bm1[j];
        for (int k = 0; k < 256; ++k) s += gv[k] * Wm1[k * 8 + j];
        hid[j] = fmaxf(s, 0.f);
    }
    #pragma unroll
    for (int c = 0; c < 2; ++c) {
        float o = bm2[c];
        #pragma unroll
        for (int j = 0; j < 8; ++j) o += hid[j] * Wm2[j * 2 + c];
        out[g * 2 + c] = o;
    }
}

// ---------------- launch ----------------
extern "C" void kernel_launch(void* const* d_in, const int* in_sizes, int n_in,
                              void* d_out, int out_size) {
    const float* x   = (const float*)d_in[0];
    const int*   ei  = (const int*)d_in[1];
    const float* ea  = (const float*)d_in[2];
    const int*   bat = (const int*)d_in[3];
    const float* W1A = (const float*)d_in[4];  const float* b1A = (const float*)d_in[5];
    const float* W1B = (const float*)d_in[6];  const float* b1B = (const float*)d_in[7];
    const float* W1C = (const float*)d_in[8];  const float* b1C = (const float*)d_in[9];
    const float* W1D = (const float*)d_in[10]; const float* b1D = (const float*)d_in[11];
    const float* W2  = (const float*)d_in[12]; const float* b2  = (const float*)d_in[13];
    const float* W3  = (const float*)d_in[14]; const float* b3  = (const float*)d_in[15];
    const float* Wm1 = (const float*)d_in[16]; const float* bm1 = (const float*)d_in[17];
    const float* Wm2 = (const float*)d_in[18]; const float* bm2 = (const float*)d_in[19];
    float* out = (float*)d_out;

    __half *xh, *h1lin, *xcat, *h2lin, *h2, *h3lin;
    unsigned short *wc_hi, *wc_lo, *w2_hi, *w2_lo, *w3_hi, *w3_lo;
    cudaGetSymbolAddress((void**)&xh,    d_xh);
    cudaGetSymbolAddress((void**)&h1lin, d_h1lin);
    cudaGetSymbolAddress((void**)&xcat,  d_xcat);
    cudaGetSymbolAddress((void**)&h2lin, d_h2lin);
    cudaGetSymbolAddress((void**)&h2,    d_h2);
    cudaGetSymbolAddress((void**)&h3lin, d_h3lin);
    cudaGetSymbolAddress((void**)&wc_hi, d_wc_hi);
    cudaGetSymbolAddress((void**)&wc_lo, d_wc_lo);
    cudaGetSymbolAddress((void**)&w2_hi, d_w2_hi);
    cudaGetSymbolAddress((void**)&w2_lo, d_w2_lo);
    cudaGetSymbolAddress((void**)&w3_hi, d_w3_hi);
    cudaGetSymbolAddress((void**)&w3_lo, d_w3_lo);

    cudaStream_t s1;
    cudaEvent_t ev0, ev1;
    cudaStreamCreateWithFlags(&s1, cudaStreamNonBlocking);
    cudaEventCreateWithFlags(&ev0, cudaEventDisableTiming);
    cudaEventCreateWithFlags(&ev1, cudaEventDisableTiming);

    const int TB = 256;
    k_init<<<196 + 896, 256>>>(W1A, W1B, W1C, W1D, W2, W3);

    cudaEventRecord(ev0, 0);
    cudaStreamWaitEvent(s1, ev0, 0);
    k_degree<<<(NE + TB - 1) / TB, TB, 0, s1>>>(ei, ea);
    k_rsqrt <<<(5 * NN + TB - 1) / TB, TB, 0, s1>>>();
    k_bsum  <<<196, 256, 0, s1>>>();
    k_bscan <<<1, 256, 0, s1>>>();
    k_scan3 <<<196, 256, 0, s1>>>();
    k_scatter<<<(NE + TB - 1) / TB, TB, 0, s1>>>(ei, ea);
    k_bounds<<<(NN + TB - 1) / TB, TB, 0, s1>>>(bat);
    cudaEventRecord(ev1, s1);

    k_x2h<<<(NN * 16 + 255) / 256, 256>>>(x);
    mma_gemm<<<dim3(4, 391), 512>>>(xh, wc_hi, wc_lo, h1lin, NN, 128, 512);

    cudaStreamWaitEvent(0, ev1, 0);

    k_agg1<<<(NN + 1) / 2, 256>>>(b1A, b1B, b1C, b1D);

    mma_gemm<<<dim3(2, 391), 512>>>(xcat, w2_hi, w2_lo, h2lin, NN, 512, 256);
    k_agg2<<<(NN + 3) / 4, 256>>>(b2);

    mma_gemm<<<dim3(1, 391), 512>>>(h2, w3_hi, w3_lo, h3lin, NN, 256, 128);
    k_agg3<<<(NN + 7) / 8, 256>>>(b3);

    k_pool<<<NG, 128>>>();
    k_mlp<<<1, NG>>>(Wm1, bm1, Wm2, bm2, out);
}

// round 14
// speedup vs baseline: 1.3084x; 1.2000x over previous
#include <cuda_runtime.h>
#include <cuda_fp16.h>
#include <math.h>
#include <cstdint>

#define NN 50000
#define NE 600000
#define NG 64

typedef unsigned long long u64;
typedef unsigned int u32;

// ---------------- scratch (device globals; allocation-free) ----------------
__device__ __half d_xh   [(size_t)NN * 128];
__device__ __half d_h1lin[(size_t)NN * 512];
__device__ __half d_xcat [(size_t)NN * 512];
__device__ __half d_h2lin[(size_t)NN * 256];
__device__ __half d_h2   [(size_t)NN * 256];
__device__ __half d_h3lin[(size_t)NN * 128];
__device__ float  d_h3   [(size_t)NN * 128];
__device__ unsigned short d_wc_h[512 * 128];   // fp16 weights (transposed)
__device__ unsigned short d_w2_h[256 * 512];
__device__ unsigned short d_w3_h[128 * 256];
__device__ float d_dis4[4 * NN];
__device__ float d_dis1[NN];
__device__ int   d_cnt[NN];
__device__ int   d_rowptr[NN + 1];
__device__ int   d_wrptr[NN];
__device__ int   d_csr_src[NE];
__device__ float4 d_csr_nrm4[NE];
__device__ float  d_csr_nrm1[NE];
__device__ int   d_bsum[256];
__device__ int   d_boff[256];
__device__ int   d_gstart[NG + 1];
__device__ float d_gmat[NG * 256];

__device__ __forceinline__ u32 smem_u32(const void* p) {
    u32 a;
    asm("{ .reg .u64 t; cvta.to.shared.u64 t, %1; cvt.u32.u64 %0, t; }" : "=r"(a) : "l"(p));
    return a;
}

__device__ __forceinline__ void mma_f16(float* d, const u32* a, const u32* b) {
    asm volatile(
        "mma.sync.aligned.m16n8k16.row.col.f32.f16.f16.f32 "
        "{%0,%1,%2,%3}, {%4,%5,%6,%7}, {%8,%9}, {%0,%1,%2,%3};"
        : "+f"(d[0]), "+f"(d[1]), "+f"(d[2]), "+f"(d[3])
        : "r"(a[0]), "r"(a[1]), "r"(a[2]), "r"(a[3]), "r"(b[0]), "r"(b[1]));
}

__device__ __forceinline__ void ldm4(u32* d, u32 addr) {
    asm volatile("ldmatrix.sync.aligned.m8n8.x4.shared.b16 {%0,%1,%2,%3}, [%4];"
        : "=r"(d[0]), "=r"(d[1]), "=r"(d[2]), "=r"(d[3]) : "r"(addr));
}

__device__ __forceinline__ void fma_h4(float4& acc, const __half* p, float n) {
    uint2 raw = *(const uint2*)p;
    __half2 p0 = *reinterpret_cast<__half2*>(&raw.x);
    __half2 p1 = *reinterpret_cast<__half2*>(&raw.y);
    float2 f0 = __half22float2(p0);
    float2 f1 = __half22float2(p1);
    acc.x += f0.x * n; acc.y += f0.y * n;
    acc.z += f1.x * n; acc.w += f1.y * n;
}

__device__ __forceinline__ void st_h4(__half* p, float4 o) {
    union { __half2 h2[2]; uint2 u; } cv;
    cv.h2[0] = __floats2half2_rn(o.x, o.y);
    cv.h2[1] = __floats2half2_rn(o.z, o.w);
    *(uint2*)p = cv.u;
}

// ---------------- setup ----------------
__global__ void k_init(const float* __restrict__ WA, const float* __restrict__ WB,
                       const float* __restrict__ WC, const float* __restrict__ WD,
                       const float* __restrict__ W2, const float* __restrict__ W3) {
    int b = blockIdx.x;
    if (b < 196) {
        int v = b * 256 + threadIdx.x;
        if (v < NN) {
            d_dis4[v] = 1.0f; d_dis4[NN + v] = 1.0f;
            d_dis4[2 * NN + v] = 1.0f; d_dis4[3 * NN + v] = 1.0f;
            d_dis1[v] = 1.0f;
        }
        return;
    }
    int i = (b - 196) * 256 + threadIdx.x;
    float v;
    if (i < 65536) {
        int n = i >> 7, kk = i & 127;
        int conv = n >> 7, c = n & 127;
        const float* W = (conv == 0) ? WA : (conv == 1) ? WB : (conv == 2) ? WC : WD;
        v = W[kk * 128 + c];
        __half hh = __float2half_rn(v);
        d_wc_h[i] = *reinterpret_cast<unsigned short*>(&hh);
    } else if (i < 65536 + 131072) {
        int j = i - 65536;
        int n = j >> 9, kk = j & 511;
        v = W2[kk * 256 + n];
        __half hh = __float2half_rn(v);
        d_w2_h[j] = *reinterpret_cast<unsigned short*>(&hh);
    } else {
        int j = i - 196608;
        int n = j >> 8, kk = j & 255;
        v = W3[kk * 128 + n];
        __half hh = __float2half_rn(v);
        d_w3_h[j] = *reinterpret_cast<unsigned short*>(&hh);
    }
}

__global__ void k_x2h(const float* __restrict__ x) {
    int i = blockIdx.x * blockDim.x + threadIdx.x;
    if (i >= NN * 16) return;
    float4 f0 = *(const float4*)(x + (size_t)i * 8);
    float4 f1 = *(const float4*)(x + (size_t)i * 8 + 4);
    union { __half2 h2[4]; uint4 u; } cv;
    cv.h2[0] = __floats2half2_rn(f0.x, f0.y);
    cv.h2[1] = __floats2half2_rn(f0.z, f0.w);
    cv.h2[2] = __floats2half2_rn(f1.x, f1.y);
    cv.h2[3] = __floats2half2_rn(f1.z, f1.w);
    *(uint4*)(d_xh + (size_t)i * 8) = cv.u;
}

__global__ void k_degree(const int* __restrict__ ei, const float* __restrict__ ea) {
    int e = blockIdx.x * blockDim.x + threadIdx.x;
    if (e >= NE) return;
    int dst = ei[NE + e];
    float4 w = __ldg((const float4*)ea + e);
    atomicAdd(&d_dis4[dst], w.x);
    atomicAdd(&d_dis4[NN + dst], w.y);
    atomicAdd(&d_dis4[2 * NN + dst], w.z);
    atomicAdd(&d_dis4[3 * NN + dst], w.w);
    atomicAdd(&d_dis1[dst], 1.0f);
}

__global__ void k_rsqrt() {
    int v = blockIdx.x * blockDim.x + threadIdx.x;
    if (v < 4 * NN) {
        d_dis4[v] = rsqrtf(d_dis4[v]);
    } else if (v < 5 * NN) {
        int u = v - 4 * NN;
        float deg = d_dis1[u];
        d_cnt[u] = (int)(deg - 0.5f);
        d_dis1[u] = rsqrtf(deg);
    }
}

// ---------------- 3-phase grid scan ----------------
__global__ void k_bsum() {
    __shared__ int ws[8];
    int idx = blockIdx.x * 256 + threadIdx.x;
    int v = (idx < NN) ? d_cnt[idx] : 0;
    int lane = threadIdx.x & 31, wid = threadIdx.x >> 5;
    int s = v;
    #pragma unroll
    for (int o = 16; o > 0; o >>= 1) s += __shfl_down_sync(0xffffffffu, s, o);
    if (lane == 0) ws[wid] = s;
    __syncthreads();
    if (wid == 0) {
        int t = (lane < 8) ? ws[lane] : 0;
        #pragma unroll
        for (int o = 4; o > 0; o >>= 1) t += __shfl_down_sync(0xffffffffu, t, o);
        if (lane == 0) d_bsum[blockIdx.x] = t;
    }
}

__global__ void k_bscan() {
    __shared__ int ws[8];
    int t = threadIdx.x;
    int lane = t & 31, wid = t >> 5;
    int v = (t < 196) ? d_bsum[t] : 0;
    int x = v;
    #pragma unroll
    for (int o = 1; o < 32; o <<= 1) {
        int y = __shfl_up_sync(0xffffffffu, x, o);
        if (lane >= o) x += y;
    }
    if (lane == 31) ws[wid] = x;
    __syncthreads();
    if (wid == 0 && lane < 8) {
        int s = ws[lane];
        #pragma unroll
        for (int o = 1; o < 8; o <<= 1) {
            int y = __shfl_up_sync(0xffu, s, o);
            if (lane >= o) s += y;
        }
        ws[lane] = s;
    }
    __syncthreads();
    int excl = x - v + (wid > 0 ? ws[wid - 1] : 0);
    if (t < 196) d_boff[t] = excl;
    if (t == 0) d_rowptr[NN] = NE;
}

__global__ void k_scan3() {
    __shared__ int ws[8];
    int idx = blockIdx.x * 256 + threadIdx.x;
    int t = threadIdx.x;
    int lane = t & 31, wid = t >> 5;
    int v = (idx < NN) ? d_cnt[idx] : 0;
    int x = v;
    #pragma unroll
    for (int o = 1; o < 32; o <<= 1) {
        int y = __shfl_up_sync(0xffffffffu, x, o);
        if (lane >= o) x += y;
    }
    if (lane == 31) ws[wid] = x;
    __syncthreads();
    if (wid == 0 && lane < 8) {
        int s = ws[lane];
        #pragma unroll
        for (int o = 1; o < 8; o <<= 1) {
            int y = __shfl_up_sync(0xffu, s, o);
            if (lane >= o) s += y;
        }
        ws[lane] = s;
    }
    __syncthreads();
    int excl = x - v + (wid > 0 ? ws[wid - 1] : 0) + d_boff[blockIdx.x];
    if (idx < NN) { d_rowptr[idx] = excl; d_wrptr[idx] = excl; }
}

__global__ void k_scatter(const int* __restrict__ ei, const float* __restrict__ ea) {
    int e = blockIdx.x * blockDim.x + threadIdx.x;
    if (e >= NE) return;
    int src = ei[e];
    int dst = ei[NE + e];
    float4 w = __ldg((const float4*)ea + e);
    int pos = atomicAdd(&d_wrptr[dst], 1);
    float4 n4;
    n4.x = d_dis4[src] * w.x * d_dis4[dst];
    n4.y = d_dis4[NN + src] * w.y * d_dis4[NN + dst];
    n4.z = d_dis4[2 * NN + src] * w.z * d_dis4[2 * NN + dst];
    n4.w = d_dis4[3 * NN + src] * w.w * d_dis4[3 * NN + dst];
    d_csr_src[pos] = src;
    d_csr_nrm4[pos] = n4;
    d_csr_nrm1[pos] = d_dis1[src] * d_dis1[dst];
}

// ============ fp16 1-term GEMM: C = A(fp16) @ B(fp16)^T, fp32 accum ============
#define KT 32
#define ASTR 40

__global__ __launch_bounds__(512, 2) void mma_gemm(
    const __half* __restrict__ A, const unsigned short* __restrict__ B,
    __half* __restrict__ C, int M, int K, int ldc)
{
    __shared__ unsigned short sA[128 * ASTR];
    __shared__ unsigned short sB[128 * ASTR];
    int tid = threadIdx.x;
    int wid = tid >> 5, lane = tid & 31;
    int g = lane >> 2, tg = lane & 3;
    int wm = wid >> 2, wn = wid & 3;
    int row0 = blockIdx.y * 128, col0 = blockIdx.x * 128;

    u32 bA = smem_u32(sA), bB = smem_u32(sB);
    u32 aOff = (u32)(((wm * 32 + (lane & 15)) * ASTR + ((lane >> 4) << 3)) * 2);
    u32 bOff = (u32)(((wn * 32 + lane) * ASTR) * 2);

    float c[2][4][4];
    #pragma unroll
    for (int mi = 0; mi < 2; mi++)
        #pragma unroll
        for (int ni = 0; ni < 4; ni++)
            #pragma unroll
            for (int q = 0; q < 4; q++) c[mi][ni][q] = 0.f;

    int rowA = tid >> 2, segA = tid & 3;
    for (int kc = 0; kc < K; kc += KT) {
        {
            int gr = row0 + rowA;
            uint4 va = make_uint4(0u, 0u, 0u, 0u);
            if (gr < M) va = *(const uint4*)(A + (size_t)gr * K + kc + segA * 8);
            *(uint4*)&sA[rowA * ASTR + segA * 8] = va;
            size_t gi = (size_t)(col0 + rowA) * K + kc + segA * 8;
            *(uint4*)&sB[rowA * ASTR + segA * 8] = *(const uint4*)(B + gi);
        }
        __syncthreads();
        #pragma unroll
        for (int ks = 0; ks < KT; ks += 16) {
            u32 ah[2][4];
            u32 bh0[4], bh1[4];
            u32 ksb = (u32)(ks * 2);
            ldm4(ah[0], bA + aOff + ksb);
            ldm4(ah[1], bA + aOff + ksb + 16 * ASTR * 2);
            ldm4(bh0, bB + bOff + ksb);
            ldm4(bh1, bB + bOff + ksb + 16);
            #pragma unroll
            for (int mi = 0; mi < 2; mi++)
                #pragma unroll
                for (int ni = 0; ni < 4; ni++) {
                    u32 bb[2] = {bh0[ni], bh1[ni]};
                    mma_f16(c[mi][ni], ah[mi], bb);
                }
        }
        __syncthreads();
    }
    #pragma unroll
    for (int mi = 0; mi < 2; mi++) {
        int r = row0 + wm * 32 + mi * 16 + g;
        #pragma unroll
        for (int ni = 0; ni < 4; ni++) {
            int cc = col0 + wn * 32 + ni * 8 + tg * 2;
            if (r < M)
                *(__half2*)(C + (size_t)r * ldc + cc) =
                    __floats2half2_rn(c[mi][ni][0], c[mi][ni][1]);
            if (r + 8 < M)
                *(__half2*)(C + (size_t)(r + 8) * ldc + cc) =
                    __floats2half2_rn(c[mi][ni][2], c[mi][ni][3]);
        }
    }
}

// ---------------- aggregation (fp16 gathers, unroll x4) ----------------
__global__ __launch_bounds__(256) void k_agg1(
    const float* __restrict__ b1A, const float* __restrict__ b1B,
    const float* __restrict__ b1C, const float* __restrict__ b1D)
{
    int v = blockIdx.x * 2 + (threadIdx.x >> 7);
    int wid = (threadIdx.x >> 5) & 3, lane = threadIdx.x & 31;
    if (v >= NN) return;
    int beg = d_rowptr[v], end = d_rowptr[v + 1];
    const float* nrm = (const float*)d_csr_nrm4;
    float4 acc = make_float4(0.f, 0.f, 0.f, 0.f);
    int p = beg;
    for (; p + 4 <= end; p += 4) {
        int s0 = d_csr_src[p],     s1 = d_csr_src[p + 1];
        int s2 = d_csr_src[p + 2], s3 = d_csr_src[p + 3];
        float n0 = __ldg(nrm + p * 4 + wid);
        float n1 = __ldg(nrm + (p + 1) * 4 + wid);
        float n2 = __ldg(nrm + (p + 2) * 4 + wid);
        float n3 = __ldg(nrm + (p + 3) * 4 + wid);
        fma_h4(acc, d_h1lin + (size_t)s0 * 512 + wid * 128 + lane * 4, n0);
        fma_h4(acc, d_h1lin + (size_t)s1 * 512 + wid * 128 + lane * 4, n1);
        fma_h4(acc, d_h1lin + (size_t)s2 * 512 + wid * 128 + lane * 4, n2);
        fma_h4(acc, d_h1lin + (size_t)s3 * 512 + wid * 128 + lane * 4, n3);
    }
    for (; p < end; ++p) {
        int s0 = d_csr_src[p];
        float n0 = __ldg(nrm + p * 4 + wid);
        fma_h4(acc, d_h1lin + (size_t)s0 * 512 + wid * 128 + lane * 4, n0);
    }
    float dv = d_dis4[wid * NN + v];
    fma_h4(acc, d_h1lin + (size_t)v * 512 + wid * 128 + lane * 4, dv * dv);
    const float* bp = (wid == 0) ? b1A : (wid == 1) ? b1B : (wid == 2) ? b1C : b1D;
    float4 bb = *(const float4*)(bp + lane * 4);
    float4 o;
    o.x = fmaxf(acc.x + bb.x, 0.f); o.y = fmaxf(acc.y + bb.y, 0.f);
    o.z = fmaxf(acc.z + bb.z, 0.f); o.w = fmaxf(acc.w + bb.w, 0.f);
    st_h4(d_xcat + (size_t)v * 512 + wid * 128 + lane * 4, o);
}

__global__ __launch_bounds__(256) void k_agg2(const float* __restrict__ b2) {
    int v = blockIdx.x * 4 + (threadIdx.x >> 6);
    int t6 = threadIdx.x & 63;
    if (v >= NN) return;
    int beg = d_rowptr[v], end = d_rowptr[v + 1];
    float4 acc = make_float4(0.f, 0.f, 0.f, 0.f);
    int p = beg;
    for (; p + 4 <= end; p += 4) {
        int s0 = d_csr_src[p],     s1 = d_csr_src[p + 1];
        int s2 = d_csr_src[p + 2], s3 = d_csr_src[p + 3];
        float n0 = __ldg(d_csr_nrm1 + p),     n1 = __ldg(d_csr_nrm1 + p + 1);
        float n2 = __ldg(d_csr_nrm1 + p + 2), n3 = __ldg(d_csr_nrm1 + p + 3);
        fma_h4(acc, d_h2lin + (size_t)s0 * 256 + t6 * 4, n0);
        fma_h4(acc, d_h2lin + (size_t)s1 * 256 + t6 * 4, n1);
        fma_h4(acc, d_h2lin + (size_t)s2 * 256 + t6 * 4, n2);
        fma_h4(acc, d_h2lin + (size_t)s3 * 256 + t6 * 4, n3);
    }
    for (; p < end; ++p) {
        int s0 = d_csr_src[p];
        float n0 = __ldg(d_csr_nrm1 + p);
        fma_h4(acc, d_h2lin + (size_t)s0 * 256 + t6 * 4, n0);
    }
    float dv = d_dis1[v];
    fma_h4(acc, d_h2lin + (size_t)v * 256 + t6 * 4, dv * dv);
    float4 bb = *(const float4*)(b2 + t6 * 4);
    float4 o;
    o.x = fmaxf(acc.x + bb.x, 0.f); o.y = fmaxf(acc.y + bb.y, 0.f);
    o.z = fmaxf(acc.z + bb.z, 0.f); o.w = fmaxf(acc.w + bb.w, 0.f);
    st_h4(d_h2 + (size_t)v * 256 + t6 * 4, o);
}

__global__ __launch_bounds__(256) void k_agg3(const float* __restrict__ b3) {
    int v = blockIdx.x * 8 + (threadIdx.x >> 5);
    int lane = threadIdx.x & 31;
    if (v >= NN) return;
    int beg = d_rowptr[v], end = d_rowptr[v + 1];
    float4 acc = make_float4(0.f, 0.f, 0.f, 0.f);
    int p = beg;
    for (; p + 4 <= end; p += 4) {
        int s0 = d_csr_src[p],     s1 = d_csr_src[p + 1];
        int s2 = d_csr_src[p + 2], s3 = d_csr_src[p + 3];
        float n0 = __ldg(d_csr_nrm1 + p),     n1 = __ldg(d_csr_nrm1 + p + 1);
        float n2 = __ldg(d_csr_nrm1 + p + 2), n3 = __ldg(d_csr_nrm1 + p + 3);
        fma_h4(acc, d_h3lin + (size_t)s0 * 128 + lane * 4, n0);
        fma_h4(acc, d_h3lin + (size_t)s1 * 128 + lane * 4, n1);
        fma_h4(acc, d_h3lin + (size_t)s2 * 128 + lane * 4, n2);
        fma_h4(acc, d_h3lin + (size_t)s3 * 128 + lane * 4, n3);
    }
    for (; p < end; ++p) {
        int s0 = d_csr_src[p];
        float n0 = __ldg(d_csr_nrm1 + p);
        fma_h4(acc, d_h3lin + (size_t)s0 * 128 + lane * 4, n0);
    }
    float dv = d_dis1[v];
    fma_h4(acc, d_h3lin + (size_t)v * 128 + lane * 4, dv * dv);
    float4 bb = *(const float4*)(b3 + lane * 4);
    float4 o;
    o.x = acc.x + bb.x; o.y = acc.y + bb.y;
    o.z = acc.z + bb.z; o.w = acc.w + bb.w;
    *(float4*)(d_h3 + (size_t)v * 128 + lane * 4) = o;
}

// ---------------- pooling + head ----------------
__global__ void k_bounds(const int* __restrict__ batch) {
    int i = blockIdx.x * blockDim.x + threadIdx.x;
    if (i >= NN) return;
    int b = batch[i];
    if (i == 0) {
        for (int g = 0; g <= b; ++g) d_gstart[g] = 0;
    } else {
        int pb = batch[i - 1];
        if (pb != b)
            for (int g = pb + 1; g <= b; ++g) d_gstart[g] = i;
    }
    if (i == NN - 1) {
        for (int g = b + 1; g <= NG; ++g) d_gstart[g] = NN;
    }
}

__global__ __launch_bounds__(128) void k_pool() {
    __shared__ float4 ssum[4][32], smax[4][32];
    int g = blockIdx.x;
    int wid = threadIdx.x >> 5, lane = threadIdx.x & 31;
    int beg = d_gstart[g], end = d_gstart[g + 1];
    int cnt = end - beg;
    float4 s = make_float4(0.f, 0.f, 0.f, 0.f);
    float4 m = make_float4(-INFINITY, -INFINITY, -INFINITY, -INFINITY);
    for (int i = beg + wid; i < end; i += 4) {
        float4 v = *(const float4*)(d_h3 + (size_t)i * 128 + lane * 4);
        s.x += v.x; s.y += v.y; s.z += v.z; s.w += v.w;
        m.x = fmaxf(m.x, v.x); m.y = fmaxf(m.y, v.y);
        m.z = fmaxf(m.z, v.z); m.w = fmaxf(m.w, v.w);
    }
    ssum[wid][lane] = s; smax[wid][lane] = m;
    __syncthreads();
    if (wid == 0) {
        #pragma unroll
        for (int w = 1; w < 4; ++w) {
            float4 s2 = ssum[w][lane], m2 = smax[w][lane];
            s.x += s2.x; s.y += s2.y; s.z += s2.z; s.w += s2.w;
            m.x = fmaxf(m.x, m2.x); m.y = fmaxf(m.y, m2.y);
            m.z = fmaxf(m.z, m2.z); m.w = fmaxf(m.w, m2.w);
        }
        float inv = 1.0f / fmaxf((float)cnt, 1.0f);
        float4 mean = make_float4(s.x * inv, s.y * inv, s.z * inv, s.w * inv);
        if (cnt == 0) m = make_float4(0.f, 0.f, 0.f, 0.f);
        *(float4*)(d_gmat + g * 256 + lane * 4) = mean;
        *(float4*)(d_gmat + g * 256 + 128 + lane * 4) = m;
    }
}

__global__ void k_mlp(const float* __restrict__ Wm1, const float* __restrict__ bm1,
                      const float* __restrict__ Wm2, const float* __restrict__ bm2,
                      float* __restrict__ out) {
    int g = threadIdx.x;
    if (g >= NG) return;
    const float* gv = d_gmat + g * 256;
    float hid[8];
    #pragma unroll
    for (int j = 0; j < 8; ++j) {
        float s = bm1[j];
        for (int k = 0; k < 256; ++k) s += gv[k] * Wm1[k * 8 + j];
        hid[j] = fmaxf(s, 0.f);
    }
    #pragma unroll
    for (int c = 0; c < 2; ++c) {
        float o = bm2[c];
        #pragma unroll
        for (int j = 0; j < 8; ++j) o += hid[j] * Wm2[j * 2 + c];
        out[g * 2 + c] = o;
    }
}

// ---------------- launch ----------------
extern "C" void kernel_launch(void* const* d_in, const int* in_sizes, int n_in,
                              void* d_out, int out_size) {
    const float* x   = (const float*)d_in[0];
    const int*   ei  = (const int*)d_in[1];
    const float* ea  = (const float*)d_in[2];
    const int*   bat = (const int*)d_in[3];
    const float* W1A = (const float*)d_in[4];  const float* b1A = (const float*)d_in[5];
    const float* W1B = (const float*)d_in[6];  const float* b1B = (const float*)d_in[7];
    const float* W1C = (const float*)d_in[8];  const float* b1C = (const float*)d_in[9];
    const float* W1D = (const float*)d_in[10]; const float* b1D = (const float*)d_in[11];
    const float* W2  = (const float*)d_in[12]; const float* b2  = (const float*)d_in[13];
    const float* W3  = (const float*)d_in[14]; const float* b3  = (const float*)d_in[15];
    const float* Wm1 = (const float*)d_in[16]; const float* bm1 = (const float*)d_in[17];
    const float* Wm2 = (const float*)d_in[18]; const float* bm2 = (const float*)d_in[19];
    float* out = (float*)d_out;

    __half *xh, *h1lin, *xcat, *h2lin, *h2, *h3lin;
    unsigned short *wc_h, *w2_h, *w3_h;
    cudaGetSymbolAddress((void**)&xh,    d_xh);
    cudaGetSymbolAddress((void**)&h1lin, d_h1lin);
    cudaGetSymbolAddress((void**)&xcat,  d_xcat);
    cudaGetSymbolAddress((void**)&h2lin, d_h2lin);
    cudaGetSymbolAddress((void**)&h2,    d_h2);
    cudaGetSymbolAddress((void**)&h3lin, d_h3lin);
    cudaGetSymbolAddress((void**)&wc_h,  d_wc_h);
    cudaGetSymbolAddress((void**)&w2_h,  d_w2_h);
    cudaGetSymbolAddress((void**)&w3_h,  d_w3_h);

    cudaStream_t s1;
    cudaEvent_t ev0, ev1;
    cudaStreamCreateWithFlags(&s1, cudaStreamNonBlocking);
    cudaEventCreateWithFlags(&ev0, cudaEventDisableTiming);
    cudaEventCreateWithFlags(&ev1, cudaEventDisableTiming);

    const int TB = 256;
    k_init<<<196 + 896, 256>>>(W1A, W1B, W1C, W1D, W2, W3);

    cudaEventRecord(ev0, 0);
    cudaStreamWaitEvent(s1, ev0, 0);
    k_degree<<<(NE + TB - 1) / TB, TB, 0, s1>>>(ei, ea);
    k_rsqrt <<<(5 * NN + TB - 1) / TB, TB, 0, s1>>>();
    k_bsum  <<<196, 256, 0, s1>>>();
    k_bscan <<<1, 256, 0, s1>>>();
    k_scan3 <<<196, 256, 0, s1>>>();
    k_scatter<<<(NE + TB - 1) / TB, TB, 0, s1>>>(ei, ea);
    k_bounds<<<(NN + TB - 1) / TB, TB, 0, s1>>>(bat);
    cudaEventRecord(ev1, s1);

    k_x2h<<<(NN * 16 + 255) / 256, 256>>>(x);
    mma_gemm<<<dim3(4, 391), 512>>>(xh, wc_h, h1lin, NN, 128, 512);

    cudaStreamWaitEvent(0, ev1, 0);

    k_agg1<<<(NN + 1) / 2, 256>>>(b1A, b1B, b1C, b1D);

    mma_gemm<<<dim3(2, 391), 512>>>(xcat, w2_h, h2lin, NN, 512, 256);
    k_agg2<<<(NN + 3) / 4, 256>>>(b2);

    mma_gemm<<<dim3(1, 391), 512>>>(h2, w3_h, h3lin, NN, 256, 128);
    k_agg3<<<(NN + 7) / 8, 256>>>(b3);

    k_pool<<<NG, 128>>>();
    k_mlp<<<1, NG>>>(Wm1, bm1, Wm2, bm2, out);
}